// round 4
// baseline (speedup 1.0000x reference)
#include <cuda_runtime.h>
#include <cstdint>

// Problem constants
#define BB   64
#define II   128
#define TT   1024
#define HH   256
#define G4   1024   // 4*H

// ---------------- scratch: pre-activations pre[b][t][4H] (256 MB) ----------
__device__ float g_pre[(size_t)BB * TT * G4];

// ---------------- helpers ----------------
__device__ __forceinline__ void ffma2(unsigned long long& d,
                                      unsigned long long a,
                                      unsigned long long b) {
    asm("fma.rn.f32x2 %0, %1, %2, %0;" : "+l"(d) : "l"(a), "l"(b));
}
__device__ __forceinline__ unsigned long long packf2(float a, float b) {
    unsigned long long r;
    asm("mov.b64 %0, {%1, %2};" : "=l"(r) : "f"(a), "f"(b));
    return r;
}
__device__ __forceinline__ float f2lo(unsigned long long v) {
    return __uint_as_float((unsigned)(v & 0xffffffffull));
}
__device__ __forceinline__ float f2hi(unsigned long long v) {
    return __uint_as_float((unsigned)(v >> 32));
}
__device__ __forceinline__ uint32_t mapa_rank(uint32_t addr, uint32_t r) {
    uint32_t out;
    asm("mapa.shared::cluster.u32 %0, %1, %2;" : "=r"(out) : "r"(addr), "r"(r));
    return out;
}
__device__ __forceinline__ void st_cluster_f32(uint32_t addr, float v) {
    asm volatile("st.shared::cluster.f32 [%0], %1;" :: "r"(addr), "f"(v) : "memory");
}
#define CLUSTER_SYNC() do { \
    asm volatile("barrier.cluster.arrive.aligned;" ::: "memory"); \
    asm volatile("barrier.cluster.wait.aligned;"   ::: "memory"); \
} while (0)

__device__ __forceinline__ float fast_sigmoid(float x) {
    return __frcp_rn(1.0f + __expf(-x));
}
__device__ __forceinline__ float fast_tanh(float x) {
    float ax = fabsf(x);
    float t  = __expf(-2.0f * ax);
    float r  = (1.0f - t) * __frcp_rn(1.0f + t);
    return copysignf(r, x);
}

// ============================================================================
// Phase 1: pre[b][t][g] = sum_i x[b,i,t] * W_ih[g,i] + b_ih[g] + b_hh[g]
// Tiling: CTA = (64 t) x (128 g), K=128 in 4 passes of 32. 256 threads,
// each thread computes 4t x 8g.
// ============================================================================
__global__ __launch_bounds__(256) void lstm_pre_kernel(
    const float* __restrict__ x,
    const float* __restrict__ W_ih,
    const float* __restrict__ b_ih,
    const float* __restrict__ b_hh)
{
    __shared__ __align__(16) float xs[32][68];    // [k][t]
    __shared__ __align__(16) float ws[32][132];   // [k][g]

    const int tid = threadIdx.x;
    const int tx  = tid & 15;    // g-group (8 g each)
    const int ty  = tid >> 4;    // t-group (4 t each)

    const int t0 = blockIdx.x * 64;
    const int g0 = blockIdx.y * 128;
    const int b  = blockIdx.z;

    const int gcol = g0 + tx * 8;

    float bias[8];
#pragma unroll
    for (int ig = 0; ig < 8; ig++)
        bias[ig] = b_ih[gcol + ig] + b_hh[gcol + ig];

    float acc[4][8];
#pragma unroll
    for (int it = 0; it < 4; it++)
#pragma unroll
        for (int ig = 0; ig < 8; ig++) acc[it][ig] = 0.0f;

    const size_t xbase = (size_t)b * II * TT;   // x[b, i, t] stride i = TT

    for (int kt = 0; kt < 4; kt++) {
        // load x tile [32 k][64 t]
#pragma unroll
        for (int idx = tid; idx < 32 * 64; idx += 256) {
            int k = idx >> 6, t = idx & 63;
            xs[k][t] = x[xbase + (size_t)(kt * 32 + k) * TT + t0 + t];
        }
        // load W tile transposed -> ws[k][g]
#pragma unroll
        for (int idx = tid; idx < 32 * 128; idx += 256) {
            int k = idx & 31, g = idx >> 5;
            ws[k][g] = W_ih[(size_t)(g0 + g) * II + kt * 32 + k];
        }
        __syncthreads();

#pragma unroll
        for (int k = 0; k < 32; k++) {
            float4 xv = *(const float4*)&xs[k][ty * 4];
            float4 wa = *(const float4*)&ws[k][tx * 8];
            float4 wb = *(const float4*)&ws[k][tx * 8 + 4];
            float xr[4] = {xv.x, xv.y, xv.z, xv.w};
            float wr[8] = {wa.x, wa.y, wa.z, wa.w, wb.x, wb.y, wb.z, wb.w};
#pragma unroll
            for (int it = 0; it < 4; it++)
#pragma unroll
                for (int ig = 0; ig < 8; ig++)
                    acc[it][ig] = fmaf(xr[it], wr[ig], acc[it][ig]);
        }
        __syncthreads();
    }

#pragma unroll
    for (int it = 0; it < 4; it++) {
        size_t orow = ((size_t)b * TT + (t0 + ty * 4 + it)) * G4 + gcol;
        float4 o1, o2;
        o1.x = acc[it][0] + bias[0]; o1.y = acc[it][1] + bias[1];
        o1.z = acc[it][2] + bias[2]; o1.w = acc[it][3] + bias[3];
        o2.x = acc[it][4] + bias[4]; o2.y = acc[it][5] + bias[5];
        o2.z = acc[it][6] + bias[6]; o2.w = acc[it][7] + bias[7];
        *(float4*)&g_pre[orow]     = o1;
        *(float4*)&g_pre[orow + 4] = o2;
    }
}

// ============================================================================
// Phase 2: recurrent LSTM scan.
// Cluster of 8 CTAs handles 4 batch elements. CTA rank r owns h-units
// [32r, 32r+32) => 128 gate rows, W_hh slice held in registers (f32x2 pairs).
// 512 threads: tid = row_local*4 + kpart, each thread does a 64-wide k-slice
// of one gate row for all 4 batches (FFMA2 packed over k-pairs).
// Pointwise (threads 0..127) updates c,h and pushes h to all 8 CTAs via DSMEM.
// ============================================================================
#define B_PER 4
#define HSEG  68                     // 64 + 4 pad (bank-conflict-free)
#define HBUF  (B_PER * 4 * HSEG)     // 1088 floats per buffer

__global__ void __cluster_dims__(8, 1, 1) __launch_bounds__(512, 1)
lstm_rec_kernel(const float* __restrict__ W_hh, float* __restrict__ out)
{
    __shared__ __align__(16) float h_s[2][HBUF];
    __shared__ __align__(16) float pre_s[2][B_PER * 128];
    __shared__ __align__(16) float gate_s[B_PER * 128];

    const int tid  = threadIdx.x;
    const int rl   = tid >> 2;         // row_local 0..127
    const int kp   = tid & 3;          // k-part 0..3
    const int unit = rl & 31;
    const int gate = rl >> 5;

    uint32_t rank;
    asm("mov.u32 %0, %%cluster_ctarank;" : "=r"(rank));
    const int clid = blockIdx.x >> 3;
    const int bg0  = clid * 4;         // first global batch of this cluster

    const int row_global = gate * HH + (int)rank * 32 + unit;

    // ---- load W_hh slice into registers as packed f32x2 pairs ----
    unsigned long long W2[32];
    {
        const float4* wrow =
            (const float4*)(W_hh + (size_t)row_global * HH + kp * 64);
#pragma unroll
        for (int j = 0; j < 16; j++) {
            float4 v = wrow[j];
            W2[2 * j]     = packf2(v.x, v.y);
            W2[2 * j + 1] = packf2(v.z, v.w);
        }
    }

    // ---- zero h buffer 0 ----
    for (int idx = tid; idx < HBUF; idx += 512) h_s[0][idx] = 0.0f;

    // ---- prefetch mapping (coalesced): pid=tid -> (b = tid>>7, rl = tid&127)
    const int  pb   = tid >> 7;
    const int  prl  = tid & 127;
    const int  prow = (prl >> 5) * HH + (int)rank * 32 + (prl & 31);
    const size_t pre_base = ((size_t)(bg0 + pb) * TT) * G4 + prow;

    // preload t=0
    pre_s[0][tid] = g_pre[pre_base];
    __syncthreads();
    CLUSTER_SYNC();

    // ---- pointwise thread state (threads 0..127) ----
    float c_reg = 0.0f;
    const int  pb2 = tid >> 5;                 // batch 0..3
    const int  pu  = tid & 31;                 // unit within rank
    const int  ug  = (int)rank * 32 + pu;      // global h unit
    const int  seg = ug >> 6;
    const int  wof = ug & 63;
    const size_t outbase =
        ((size_t)(bg0 + pb2) * HH + ug) * TT;  // out[b][ug][t]
    const int hofs_base = (pb2 * 4 + seg) * HSEG + wof;

    int cur = 0;
    for (int t = 0; t < TT; t++) {
        // prefetch next step's pre into a register (hidden under compute)
        float pre_next = 0.0f;
        if (t + 1 < TT) pre_next = g_pre[pre_base + (size_t)(t + 1) * G4];

        // ---- gate GEMV: 4 batches, FFMA2 over packed k-pairs ----
        float acc_keep = 0.0f;
#pragma unroll
        for (int b = 0; b < B_PER; b++) {
            const ulonglong2* hp = reinterpret_cast<const ulonglong2*>(
                &h_s[cur][(b * 4 + kp) * HSEG]);
            unsigned long long a0 = 0ull, a1 = 0ull;
#pragma unroll
            for (int j = 0; j < 16; j++) {
                ulonglong2 hv = hp[j];
                ffma2(a0, W2[2 * j],     hv.x);
                ffma2(a1, W2[2 * j + 1], hv.y);
            }
            float s = (f2lo(a0) + f2hi(a0)) + (f2lo(a1) + f2hi(a1));
            s += __shfl_xor_sync(0xffffffffu, s, 1);
            s += __shfl_xor_sync(0xffffffffu, s, 2);
            if (kp == b) acc_keep = s;
        }
        // this thread is responsible for batch b == kp
        gate_s[kp * 128 + rl] = acc_keep + pre_s[cur][kp * 128 + rl];
        pre_s[cur ^ 1][tid] = pre_next;
        __syncthreads();

        // ---- pointwise LSTM cell + h broadcast ----
        if (tid < 128) {
            float gi = gate_s[pb2 * 128 +  0 + pu];
            float gf = gate_s[pb2 * 128 + 32 + pu];
            float gg = gate_s[pb2 * 128 + 64 + pu];
            float go = gate_s[pb2 * 128 + 96 + pu];
            float i = fast_sigmoid(gi);
            float f = fast_sigmoid(gf);
            float g = fast_tanh(gg);
            float o = fast_sigmoid(go);
            c_reg = fmaf(f, c_reg, i * g);
            float h = o * fast_tanh(c_reg);
            out[outbase + t] = fmaxf(h, 0.0f);

            uint32_t laddr = (uint32_t)__cvta_generic_to_shared(
                &h_s[cur ^ 1][hofs_base]);
#pragma unroll
            for (uint32_t r = 0; r < 8; r++)
                st_cluster_f32(mapa_rank(laddr, r), h);
        }
        CLUSTER_SYNC();
        cur ^= 1;
    }
}

// ============================================================================
extern "C" void kernel_launch(void* const* d_in, const int* in_sizes, int n_in,
                              void* d_out, int out_size)
{
    const float* x    = (const float*)d_in[0];
    const float* W_ih = (const float*)d_in[1];
    const float* W_hh = (const float*)d_in[2];
    const float* b_ih = (const float*)d_in[3];
    const float* b_hh = (const float*)d_in[4];
    float* out = (float*)d_out;

    dim3 g1(TT / 64, G4 / 128, BB);   // 16 x 8 x 64
    lstm_pre_kernel<<<g1, 256>>>(x, W_ih, b_ih, b_hh);

    lstm_rec_kernel<<<128, 512>>>(W_hh, out);   // 16 clusters of 8 CTAs
}